// round 1
// baseline (speedup 1.0000x reference)
#include <cuda_runtime.h>
#include <math.h>

#define NN 50000
#define EE 800000
#define GG 32
#define DD 64
#define HH 128

// ---------------- scratch (device globals; no allocations) ----------------
__device__ float g_nPost[NN * DD];   // softplus(node_feat @ bn_W + bn_b)
__device__ float g_sPost[GG * DD];   // softplus(state_feat @ bs_W + bs_b)
__device__ float g_accN[NN * DD];    // sum of edge_update per dst node
__device__ int   g_cntN[NN];         // edge count per dst node
__device__ float g_accEG[GG * DD];   // sum of edge_update per graph (batch[src])
__device__ int   g_cntEG[GG];
__device__ float g_accNG[GG * DD];   // sum of node_update per graph
__device__ int   g_cntNG[GG];

__device__ __forceinline__ float sp(float x) {
    // softplus = logaddexp(x, 0) = max(x,0) + log1p(exp(-|x|))
    return fmaxf(x, 0.0f) + log1pf(__expf(-fabsf(x)));
}

__device__ __forceinline__ void fma_row16(float* A, float x, const float* w) {
#pragma unroll
    for (int q = 0; q < 16; q++) {
        float4 wv = *(const float4*)(w + q * 4);
        A[q * 4 + 0] += x * wv.x;
        A[q * 4 + 1] += x * wv.y;
        A[q * 4 + 2] += x * wv.z;
        A[q * 4 + 3] += x * wv.w;
    }
}

__device__ __forceinline__ void fma_row8(float* A, float x, const float* w) {
#pragma unroll
    for (int q = 0; q < 8; q++) {
        float4 wv = *(const float4*)(w + q * 4);
        A[q * 4 + 0] += x * wv.x;
        A[q * 4 + 1] += x * wv.y;
        A[q * 4 + 2] += x * wv.z;
        A[q * 4 + 3] += x * wv.w;
    }
}

// ---------------- kernel: zero accumulators ----------------
__global__ void k_zero() {
    int i = blockIdx.x * blockDim.x + threadIdx.x;
    int stride = gridDim.x * blockDim.x;
    for (int idx = i; idx < NN * DD; idx += stride) g_accN[idx] = 0.0f;
    for (int idx = i; idx < NN; idx += stride) g_cntN[idx] = 0;
    for (int idx = i; idx < GG * DD; idx += stride) { g_accEG[idx] = 0.0f; g_accNG[idx] = 0.0f; }
    for (int idx = i; idx < GG; idx += stride) { g_cntEG[idx] = 0; g_cntNG[idx] = 0; }
}

// ---------------- kernel: s_post = softplus(state_feat @ bs_W + bs_b) ----------------
__global__ __launch_bounds__(256) void k_spost(const float* __restrict__ sf,
                                               const float* __restrict__ W,
                                               const float* __restrict__ b) {
    int t = threadIdx.x;
    int g = t >> 3;            // 0..31
    int jb = (t & 7) * 8;      // 0..56
    float a[8];
#pragma unroll
    for (int u = 0; u < 8; u++) a[u] = __ldg(b + jb + u);
    for (int k = 0; k < 64; k++) {
        float x = __ldg(sf + g * 64 + k);
#pragma unroll
        for (int u = 0; u < 8; u++) a[u] += x * __ldg(W + k * 64 + jb + u);
    }
#pragma unroll
    for (int u = 0; u < 8; u++) g_sPost[g * 64 + jb + u] = sp(a[u]);
}

// ---------------- kernel: n_post = softplus(node_feat @ bn_W + bn_b) ----------------
__global__ __launch_bounds__(256) void k_npost(const float* __restrict__ nf,
                                               const float* __restrict__ W,
                                               const float* __restrict__ b) {
    extern __shared__ float sm[];
    float* xN = sm;            // 64*128
    float* wS = sm + 8192;     // 64*64
    int t = threadIdx.x;
    int n0 = blockIdx.x * 128;

    {
        int r = t >> 1, h = t & 1;
        int row = min(n0 + r, NN - 1);
        const float4* p = (const float4*)(nf + (size_t)row * 64) + h * 8;
#pragma unroll
        for (int i = 0; i < 8; i++) {
            float4 v = p[i];
            int k = h * 32 + i * 4;
            xN[(k + 0) * 128 + r] = v.x;
            xN[(k + 1) * 128 + r] = v.y;
            xN[(k + 2) * 128 + r] = v.z;
            xN[(k + 3) * 128 + r] = v.w;
        }
    }
    for (int idx = t * 4; idx < 4096; idx += 1024)
        *(float4*)(wS + idx) = *(const float4*)(W + idx);
    __syncthreads();

    int e = t & 127, half = t >> 7;
    int j0 = half * 32;
    float a[32];
#pragma unroll
    for (int q = 0; q < 8; q++) {
        float4 bv = *(const float4*)(b + j0 + q * 4);
        a[q * 4 + 0] = bv.x; a[q * 4 + 1] = bv.y; a[q * 4 + 2] = bv.z; a[q * 4 + 3] = bv.w;
    }
#pragma unroll 2
    for (int k = 0; k < 64; k++)
        fma_row8(a, xN[k * 128 + e], wS + k * 64 + j0);

    int row = n0 + e;
    if (row < NN) {
        float4* o = (float4*)(g_nPost + (size_t)row * 64 + j0);
#pragma unroll
        for (int q = 0; q < 8; q++) {
            float4 v;
            v.x = sp(a[q * 4 + 0]); v.y = sp(a[q * 4 + 1]);
            v.z = sp(a[q * 4 + 2]); v.w = sp(a[q * 4 + 3]);
            o[q] = v;
        }
    }
}

// ---------------- kernel: edge megakernel ----------------
// per tile of 128 edges: gather n_src/n_dst/s_g, fuse be MLP + 3-layer edge MLP,
// write edge output (+skip), scatter-add to node acc and graph acc.
__global__ __launch_bounds__(256) void k_edge(
    const float* __restrict__ ef, const int* __restrict__ srcI, const int* __restrict__ dstI,
    const int* __restrict__ batch,
    const float* __restrict__ beW, const float* __restrict__ beB,
    const float* __restrict__ W0, const float* __restrict__ b0,
    const float* __restrict__ W1, const float* __restrict__ b1,
    const float* __restrict__ W2, const float* __restrict__ b2,
    float* __restrict__ outE) {
    extern __shared__ float sm[];
    float* xA = sm;                 // [64][128] n_src (transposed)
    float* xB = xA + 8192;          // [64][128] n_dst
    float* xE = xB + 8192;          // [64][128] raw edge feat, later e=softplus(be)
    float* hS = xE + 8192;          // [128][128] hidden
    float* wS = hS + 16384;         // [64][128] weight staging (8192 floats)
    float* sgS = wS + 8192;         // [32][65] s_post table (padded)
    float* accG = sgS + 2080;       // [32][65] per-block graph accumulator (padded)
    int* sIdx = (int*)(accG + 2080);
    int* dIdx = sIdx + 128;
    int* gix = dIdx + 128;
    int* cg = gix + 128;            // [32]

    int t = threadIdx.x;
    int e0 = blockIdx.x * 128;

    if (t < 128) {
        int eidx = min(e0 + t, EE - 1);
        int s_ = srcI[eidx];
        sIdx[t] = s_;
        dIdx[t] = dstI[eidx];
        gix[t] = batch[s_];
    }
    for (int idx = t; idx < GG * DD; idx += 256)
        sgS[(idx >> 6) * 65 + (idx & 63)] = g_sPost[idx];
    for (int idx = t; idx < 2080; idx += 256) accG[idx] = 0.0f;
    if (t < GG) cg[t] = 0;
    __syncthreads();

    {
        int r = t >> 1, h = t & 1;
        size_t eg = (size_t)min(e0 + r, EE - 1);
        const float4* pA = (const float4*)(g_nPost + (size_t)sIdx[r] * 64) + h * 8;
        const float4* pB = (const float4*)(g_nPost + (size_t)dIdx[r] * 64) + h * 8;
        const float4* pE = (const float4*)(ef + eg * 64) + h * 8;
#pragma unroll
        for (int i = 0; i < 8; i++) {
            float4 vA = pA[i], vB = pB[i], vE = pE[i];
            int k = h * 32 + i * 4;
            xA[(k + 0) * 128 + r] = vA.x; xA[(k + 1) * 128 + r] = vA.y;
            xA[(k + 2) * 128 + r] = vA.z; xA[(k + 3) * 128 + r] = vA.w;
            xB[(k + 0) * 128 + r] = vB.x; xB[(k + 1) * 128 + r] = vB.y;
            xB[(k + 2) * 128 + r] = vB.z; xB[(k + 3) * 128 + r] = vB.w;
            xE[(k + 0) * 128 + r] = vE.x; xE[(k + 1) * 128 + r] = vE.y;
            xE[(k + 2) * 128 + r] = vE.z; xE[(k + 3) * 128 + r] = vE.w;
        }
    }
    // stage be_W (64x64)
    for (int idx = t * 4; idx < 4096; idx += 1024)
        *(float4*)(wS + idx) = *(const float4*)(beW + idx);
    __syncthreads();

    int e = t & 127, half = t >> 7;

    // ---- be MLP: e = softplus(raw @ beW + beB), written back into xE ----
    {
        int j0 = half * 32;
        float a[32];
#pragma unroll
        for (int q = 0; q < 8; q++) {
            float4 bv = *(const float4*)(beB + j0 + q * 4);
            a[q * 4 + 0] = bv.x; a[q * 4 + 1] = bv.y; a[q * 4 + 2] = bv.z; a[q * 4 + 3] = bv.w;
        }
#pragma unroll 2
        for (int k = 0; k < 64; k++)
            fma_row8(a, xE[k * 128 + e], wS + k * 64 + j0);
        __syncthreads();   // all raw-xE reads complete
#pragma unroll
        for (int u = 0; u < 32; u++) xE[(j0 + u) * 128 + e] = sp(a[u]);
    }

    // ---- layer0: [n_src | n_dst | e | s_g] (256) -> 128 ----
    float A[64];
    {
        int j0 = half * 64;
#pragma unroll
        for (int q = 0; q < 16; q++) {
            float4 bv = *(const float4*)(b0 + j0 + q * 4);
            A[q * 4 + 0] = bv.x; A[q * 4 + 1] = bv.y; A[q * 4 + 2] = bv.z; A[q * 4 + 3] = bv.w;
        }
#pragma unroll
        for (int s = 0; s < 4; s++) {
            __syncthreads();
            const float* Wsrc = W0 + s * 64 * 128;
            for (int idx = t * 4; idx < 8192; idx += 1024)
                *(float4*)(wS + idx) = *(const float4*)(Wsrc + idx);
            __syncthreads();
            if (s < 3) {
                const float* xbuf = (s == 0) ? xA : ((s == 1) ? xB : xE);
#pragma unroll 2
                for (int k = 0; k < 64; k++)
                    fma_row16(A, xbuf[k * 128 + e], wS + k * 128 + j0);
            } else {
                const float* srow = sgS + gix[e] * 65;
#pragma unroll 2
                for (int k = 0; k < 64; k++)
                    fma_row16(A, srow[k], wS + k * 128 + j0);
            }
        }
        __syncthreads();
#pragma unroll
        for (int u = 0; u < 64; u++) hS[(j0 + u) * 128 + e] = sp(A[u]);
        __syncthreads();
    }

    // ---- layer1: 128 -> 128 ----
    {
        int j0 = half * 64;
#pragma unroll
        for (int q = 0; q < 16; q++) {
            float4 bv = *(const float4*)(b1 + j0 + q * 4);
            A[q * 4 + 0] = bv.x; A[q * 4 + 1] = bv.y; A[q * 4 + 2] = bv.z; A[q * 4 + 3] = bv.w;
        }
#pragma unroll
        for (int s = 0; s < 2; s++) {
            __syncthreads();
            const float* Wsrc = W1 + s * 64 * 128;
            for (int idx = t * 4; idx < 8192; idx += 1024)
                *(float4*)(wS + idx) = *(const float4*)(Wsrc + idx);
            __syncthreads();
#pragma unroll 2
            for (int k = 0; k < 64; k++)
                fma_row16(A, hS[(s * 64 + k) * 128 + e], wS + k * 128 + j0);
        }
        __syncthreads();   // all hS reads complete before in-place overwrite
#pragma unroll
        for (int u = 0; u < 64; u++) hS[(j0 + u) * 128 + e] = sp(A[u]);
        __syncthreads();
    }

    // ---- layer2: 128 -> 64 ----
    float upd[32];
    {
        for (int idx = t * 4; idx < 8192; idx += 1024)
            *(float4*)(wS + idx) = *(const float4*)(W2 + idx);
        __syncthreads();
        int j0 = half * 32;
        float C[32];
#pragma unroll
        for (int q = 0; q < 8; q++) {
            float4 bv = *(const float4*)(b2 + j0 + q * 4);
            C[q * 4 + 0] = bv.x; C[q * 4 + 1] = bv.y; C[q * 4 + 2] = bv.z; C[q * 4 + 3] = bv.w;
        }
#pragma unroll 2
        for (int k = 0; k < 128; k++)
            fma_row8(C, hS[k * 128 + e], wS + k * 64 + j0);
#pragma unroll
        for (int u = 0; u < 32; u++) upd[u] = sp(C[u]);
    }

    // ---- epilogue ----
    int egl = e0 + e;
    int j0 = half * 32;
    if (egl < EE) {
        const float4* pref = (const float4*)(ef + (size_t)egl * 64 + j0);
        float4* po = (float4*)(outE + (size_t)egl * 64 + j0);
#pragma unroll
        for (int q = 0; q < 8; q++) {
            float4 r = pref[q];
            r.x += upd[q * 4 + 0]; r.y += upd[q * 4 + 1];
            r.z += upd[q * 4 + 2]; r.w += upd[q * 4 + 3];
            po[q] = r;
        }
        int d = dIdx[e];
        float* an = g_accN + (size_t)d * 64 + j0;
#pragma unroll
        for (int u = 0; u < 32; u++) atomicAdd(an + u, upd[u]);
        if (half == 0) atomicAdd(&g_cntN[d], 1);
        int g = gix[e];
        float* ag = accG + g * 65 + j0;
#pragma unroll
        for (int u = 0; u < 32; u++) atomicAdd(ag + u, upd[u]);
        if (half == 0) atomicAdd(&cg[g], 1);
    }
    __syncthreads();
    for (int idx = t; idx < GG * DD; idx += 256)
        atomicAdd(&g_accEG[idx], accG[(idx >> 6) * 65 + (idx & 63)]);
    if (t < GG) atomicAdd(&g_cntEG[t], cg[t]);
}

// ---------------- kernel: node megakernel ----------------
__global__ __launch_bounds__(256) void k_node(
    const float* __restrict__ nf, const int* __restrict__ batch,
    const float* __restrict__ W0, const float* __restrict__ b0,
    const float* __restrict__ W1, const float* __restrict__ b1,
    const float* __restrict__ W2, const float* __restrict__ b2,
    float* __restrict__ outN) {
    extern __shared__ float sm[];
    float* xN = sm;             // [64][128] n_post
    float* xV = xN + 8192;      // [64][128] ve
    float* hS = xV + 8192;      // [128][128]
    float* wS = hS + 16384;     // 8192
    float* sgS = wS + 8192;     // [32][65]
    float* accG = sgS + 2080;   // [32][65]
    int* gix = (int*)(accG + 2080);
    int* cg = gix + 128;

    int t = threadIdx.x;
    int n0 = blockIdx.x * 128;

    if (t < 128) {
        int ni = min(n0 + t, NN - 1);
        gix[t] = batch[ni];
    }
    for (int idx = t; idx < GG * DD; idx += 256)
        sgS[(idx >> 6) * 65 + (idx & 63)] = g_sPost[idx];
    for (int idx = t; idx < 2080; idx += 256) accG[idx] = 0.0f;
    if (t < GG) cg[t] = 0;
    __syncthreads();

    {
        int r = t >> 1, h = t & 1;
        int ni = min(n0 + r, NN - 1);
        float inv = 1.0f / fmaxf((float)g_cntN[ni], 1.0f);
        const float4* pN = (const float4*)(g_nPost + (size_t)ni * 64) + h * 8;
        const float4* pV = (const float4*)(g_accN + (size_t)ni * 64) + h * 8;
#pragma unroll
        for (int i = 0; i < 8; i++) {
            float4 vN = pN[i], vV = pV[i];
            int k = h * 32 + i * 4;
            xN[(k + 0) * 128 + r] = vN.x; xN[(k + 1) * 128 + r] = vN.y;
            xN[(k + 2) * 128 + r] = vN.z; xN[(k + 3) * 128 + r] = vN.w;
            xV[(k + 0) * 128 + r] = vV.x * inv; xV[(k + 1) * 128 + r] = vV.y * inv;
            xV[(k + 2) * 128 + r] = vV.z * inv; xV[(k + 3) * 128 + r] = vV.w * inv;
        }
    }
    __syncthreads();

    int e = t & 127, half = t >> 7;

    float A[64];
    {
        int j0 = half * 64;
#pragma unroll
        for (int q = 0; q < 16; q++) {
            float4 bv = *(const float4*)(b0 + j0 + q * 4);
            A[q * 4 + 0] = bv.x; A[q * 4 + 1] = bv.y; A[q * 4 + 2] = bv.z; A[q * 4 + 3] = bv.w;
        }
#pragma unroll
        for (int s = 0; s < 3; s++) {
            __syncthreads();
            const float* Wsrc = W0 + s * 64 * 128;
            for (int idx = t * 4; idx < 8192; idx += 1024)
                *(float4*)(wS + idx) = *(const float4*)(Wsrc + idx);
            __syncthreads();
            if (s < 2) {
                const float* xbuf = (s == 0) ? xN : xV;
#pragma unroll 2
                for (int k = 0; k < 64; k++)
                    fma_row16(A, xbuf[k * 128 + e], wS + k * 128 + j0);
            } else {
                const float* srow = sgS + gix[e] * 65;
#pragma unroll 2
                for (int k = 0; k < 64; k++)
                    fma_row16(A, srow[k], wS + k * 128 + j0);
            }
        }
        __syncthreads();
#pragma unroll
        for (int u = 0; u < 64; u++) hS[(j0 + u) * 128 + e] = sp(A[u]);
        __syncthreads();
    }
    {
        int j0 = half * 64;
#pragma unroll
        for (int q = 0; q < 16; q++) {
            float4 bv = *(const float4*)(b1 + j0 + q * 4);
            A[q * 4 + 0] = bv.x; A[q * 4 + 1] = bv.y; A[q * 4 + 2] = bv.z; A[q * 4 + 3] = bv.w;
        }
#pragma unroll
        for (int s = 0; s < 2; s++) {
            __syncthreads();
            const float* Wsrc = W1 + s * 64 * 128;
            for (int idx = t * 4; idx < 8192; idx += 1024)
                *(float4*)(wS + idx) = *(const float4*)(Wsrc + idx);
            __syncthreads();
#pragma unroll 2
            for (int k = 0; k < 64; k++)
                fma_row16(A, hS[(s * 64 + k) * 128 + e], wS + k * 128 + j0);
        }
        __syncthreads();
#pragma unroll
        for (int u = 0; u < 64; u++) hS[(j0 + u) * 128 + e] = sp(A[u]);
        __syncthreads();
    }
    float upd[32];
    {
        for (int idx = t * 4; idx < 8192; idx += 1024)
            *(float4*)(wS + idx) = *(const float4*)(W2 + idx);
        __syncthreads();
        int j0 = half * 32;
        float C[32];
#pragma unroll
        for (int q = 0; q < 8; q++) {
            float4 bv = *(const float4*)(b2 + j0 + q * 4);
            C[q * 4 + 0] = bv.x; C[q * 4 + 1] = bv.y; C[q * 4 + 2] = bv.z; C[q * 4 + 3] = bv.w;
        }
#pragma unroll 2
        for (int k = 0; k < 128; k++)
            fma_row8(C, hS[k * 128 + e], wS + k * 64 + j0);
#pragma unroll
        for (int u = 0; u < 32; u++) upd[u] = sp(C[u]);
    }

    int ni = n0 + e;
    int j0 = half * 32;
    if (ni < NN) {
        const float4* pref = (const float4*)(nf + (size_t)ni * 64 + j0);
        float4* po = (float4*)(outN + (size_t)ni * 64 + j0);
#pragma unroll
        for (int q = 0; q < 8; q++) {
            float4 r = pref[q];
            r.x += upd[q * 4 + 0]; r.y += upd[q * 4 + 1];
            r.z += upd[q * 4 + 2]; r.w += upd[q * 4 + 3];
            po[q] = r;
        }
        int g = gix[e];
        float* ag = accG + g * 65 + j0;
#pragma unroll
        for (int u = 0; u < 32; u++) atomicAdd(ag + u, upd[u]);
        if (half == 0) atomicAdd(&cg[g], 1);
    }
    __syncthreads();
    for (int idx = t; idx < GG * DD; idx += 256)
        atomicAdd(&g_accNG[idx], accG[(idx >> 6) * 65 + (idx & 63)]);
    if (t < GG) atomicAdd(&g_cntNG[t], cg[t]);
}

// ---------------- kernel: state MLP (single block) ----------------
__global__ __launch_bounds__(256) void k_stateMLP(
    const float* __restrict__ sf,
    const float* __restrict__ W0, const float* __restrict__ b0,
    const float* __restrict__ W1, const float* __restrict__ b1,
    const float* __restrict__ W2, const float* __restrict__ b2,
    float* __restrict__ outS) {
    extern __shared__ float sm[];
    float* Wst = sm;              // up to 192*128 = 24576
    float* xs = Wst + 24576;      // 32*192
    float* hs = xs + 6144;        // 32*128
    int t = threadIdx.x;

    for (int idx = t; idx < GG * DD; idx += 256) {
        int g = idx >> 6, k = idx & 63;
        xs[g * 192 + k] = g_sPost[idx];
        float ce = fmaxf((float)g_cntEG[g], 1.0f);
        xs[g * 192 + 64 + k] = g_accEG[idx] / ce;
        float cn = fmaxf((float)g_cntNG[g], 1.0f);
        xs[g * 192 + 128 + k] = g_accNG[idx] / cn;
    }
    __syncthreads();
    for (int idx = t * 4; idx < 24576; idx += 1024)
        *(float4*)(Wst + idx) = *(const float4*)(W0 + idx);
    __syncthreads();

    int g = t >> 3;
    int jb = (t & 7) * 16;
    float a[16];
#pragma unroll
    for (int u = 0; u < 16; u++) a[u] = __ldg(b0 + jb + u);
    for (int k = 0; k < 192; k++) {
        float x = xs[g * 192 + k];
#pragma unroll
        for (int u = 0; u < 16; u++) a[u] += x * Wst[k * 128 + jb + u];
    }
    __syncthreads();
#pragma unroll
    for (int u = 0; u < 16; u++) hs[g * 128 + jb + u] = sp(a[u]);
    __syncthreads();

    for (int idx = t * 4; idx < 16384; idx += 1024)
        *(float4*)(Wst + idx) = *(const float4*)(W1 + idx);
    __syncthreads();
#pragma unroll
    for (int u = 0; u < 16; u++) a[u] = __ldg(b1 + jb + u);
    for (int k = 0; k < 128; k++) {
        float x = hs[g * 128 + k];
#pragma unroll
        for (int u = 0; u < 16; u++) a[u] += x * Wst[k * 128 + jb + u];
    }
    __syncthreads();
#pragma unroll
    for (int u = 0; u < 16; u++) hs[g * 128 + jb + u] = sp(a[u]);
    __syncthreads();

    for (int idx = t * 4; idx < 8192; idx += 1024)
        *(float4*)(Wst + idx) = *(const float4*)(W2 + idx);
    __syncthreads();
    int jb2 = (t & 7) * 8;
    float c[8];
#pragma unroll
    for (int u = 0; u < 8; u++) c[u] = __ldg(b2 + jb2 + u);
    for (int k = 0; k < 128; k++) {
        float x = hs[g * 128 + k];
#pragma unroll
        for (int u = 0; u < 8; u++) c[u] += x * Wst[k * 64 + jb2 + u];
    }
#pragma unroll
    for (int u = 0; u < 8; u++)
        outS[g * 64 + jb2 + u] = sp(c[u]) + __ldg(sf + g * 64 + jb2 + u);
}

// ---------------- launcher ----------------
extern "C" void kernel_launch(void* const* d_in, const int* in_sizes, int n_in,
                              void* d_out, int out_size) {
    const float* edge_feat  = (const float*)d_in[0];
    const float* node_feat  = (const float*)d_in[1];
    const float* state_feat = (const float*)d_in[2];
    const int*   edge_index = (const int*)d_in[3];
    const int*   batch      = (const int*)d_in[4];
    const float* beW = (const float*)d_in[5];
    const float* beB = (const float*)d_in[6];
    const float* bnW = (const float*)d_in[7];
    const float* bnB = (const float*)d_in[8];
    const float* bsW = (const float*)d_in[9];
    const float* bsB = (const float*)d_in[10];
    const float* ceW0 = (const float*)d_in[11];
    const float* ceB0 = (const float*)d_in[12];
    const float* ceW1 = (const float*)d_in[13];
    const float* ceB1 = (const float*)d_in[14];
    const float* ceW2 = (const float*)d_in[15];
    const float* ceB2 = (const float*)d_in[16];
    const float* cnW0 = (const float*)d_in[17];
    const float* cnB0 = (const float*)d_in[18];
    const float* cnW1 = (const float*)d_in[19];
    const float* cnB1 = (const float*)d_in[20];
    const float* cnW2 = (const float*)d_in[21];
    const float* cnB2 = (const float*)d_in[22];
    const float* csW0 = (const float*)d_in[23];
    const float* csB0 = (const float*)d_in[24];
    const float* csW1 = (const float*)d_in[25];
    const float* csB1 = (const float*)d_in[26];
    const float* csW2 = (const float*)d_in[27];
    const float* csB2 = (const float*)d_in[28];

    const int* srcI = edge_index;
    const int* dstI = edge_index + EE;

    float* outE = (float*)d_out;
    float* outN = outE + (size_t)EE * 64;
    float* outS = outN + (size_t)NN * 64;

    size_t smNP = (8192 + 4096) * sizeof(float);
    size_t smE  = (8192 * 3 + 16384 + 8192 + 2080 + 2080) * sizeof(float) + (128 * 3 + 32) * sizeof(int);
    size_t smN  = (8192 * 2 + 16384 + 8192 + 2080 + 2080) * sizeof(float) + (128 + 32) * sizeof(int);
    size_t smS  = (24576 + 6144 + 4096) * sizeof(float);

    cudaFuncSetAttribute(k_npost, cudaFuncAttributeMaxDynamicSharedMemorySize, (int)smNP);
    cudaFuncSetAttribute(k_edge, cudaFuncAttributeMaxDynamicSharedMemorySize, (int)smE);
    cudaFuncSetAttribute(k_node, cudaFuncAttributeMaxDynamicSharedMemorySize, (int)smN);
    cudaFuncSetAttribute(k_stateMLP, cudaFuncAttributeMaxDynamicSharedMemorySize, (int)smS);

    k_zero<<<3125, 1024>>>();
    k_spost<<<1, 256>>>(state_feat, bsW, bsB);
    k_npost<<<(NN + 127) / 128, 256, smNP>>>(node_feat, bnW, bnB);
    k_edge<<<(EE + 127) / 128, 256, smE>>>(edge_feat, srcI, dstI, batch,
                                           beW, beB, ceW0, ceB0, ceW1, ceB1, ceW2, ceB2, outE);
    k_node<<<(NN + 127) / 128, 256, smN>>>(node_feat, batch,
                                           cnW0, cnB0, cnW1, cnB1, cnW2, cnB2, outN);
    k_stateMLP<<<1, 256, smS>>>(state_feat, csW0, csB0, csW1, csB1, csW2, csB2, outS);
}